// round 15
// baseline (speedup 1.0000x reference)
#include <cuda_runtime.h>
#include <cuda_bf16.h>
#include <cuda_fp16.h>
#include <cstdint>

#define EMB 128
#define MAX_ATOMS 20000
#define AP 136                      // padded row stride (fp16 elems) = 272 B
#define MROWS 96                    // rows per MLP CTA (6 m16 tiles), 2 CTAs/SM

// ---------------------------------------------------------------------------
// g_node zero-initialized at module load; mlp_kernel re-zeros as it consumes,
// so it is zero at every kernel_launch entry (deterministic).
// ---------------------------------------------------------------------------
__device__ __align__(16) float g_node[MAX_ATOMS * EMB];
__device__ __align__(16) __half g_wh[4 * 128 * AP];         // [layer][n*AP+k] fp16 weights
__device__ int g_is64;

// ---------------------------------------------------------------------------
__device__ __forceinline__ uint32_t smem_to_u32(const void* p) {
    uint32_t a;
    asm("{ .reg .u64 t; cvta.to.shared.u64 t, %1; cvt.u32.u64 %0, t; }" : "=r"(a) : "l"(p));
    return a;
}

__device__ __forceinline__ void ldsm_x4(uint32_t addr, uint32_t r[4]) {
    asm volatile("ldmatrix.sync.aligned.m8n8.x4.shared.b16 {%0,%1,%2,%3}, [%4];"
                 : "=r"(r[0]), "=r"(r[1]), "=r"(r[2]), "=r"(r[3]) : "r"(addr));
}

__device__ __forceinline__ void mma16816h(float d[4], const uint32_t a[4],
                                          uint32_t b0, uint32_t b1) {
    asm volatile(
        "mma.sync.aligned.m16n8k16.row.col.f32.f16.f16.f32 "
        "{%0,%1,%2,%3}, {%4,%5,%6,%7}, {%8,%9}, {%0,%1,%2,%3};"
        : "+f"(d[0]), "+f"(d[1]), "+f"(d[2]), "+f"(d[3])
        : "r"(a[0]), "r"(a[1]), "r"(a[2]), "r"(a[3]), "r"(b0), "r"(b1));
}

__device__ __forceinline__ uint32_t pack_h2(float x, float y) {
    __half2 v;
    v.x = __float2half_rn(x);
    v.y = __float2half_rn(y);
    return *reinterpret_cast<uint32_t*>(&v);
}

__device__ __forceinline__ void cp_async16(uint32_t smem_addr, const void* gptr) {
    asm volatile("cp.async.cg.shared.global [%0], [%1], 16;"
                 :: "r"(smem_addr), "l"(gptr));
}
__device__ __forceinline__ void cp_async_commit() {
    asm volatile("cp.async.commit_group;" ::: "memory");
}
__device__ __forceinline__ void cp_async_wait0() {
    asm volatile("cp.async.wait_group 0;" ::: "memory");
}

// fast swish: x * sigmoid(x) via EX2 + RCP (no IEEE div)
__device__ __forceinline__ float fast_swish(float x) {
    float e = __expf(-x);
    return __fdividef(x, 1.0f + e);
}

// ---------------------------------------------------------------------------
// Setup (33 blocks): weight prep (coalesced 16B writes) + dtype detect.
// No zero pass — g_node zero is maintained by the mlp kernel invariant.
// ---------------------------------------------------------------------------
__global__ void setup_kernel(const float* __restrict__ W1, const float* __restrict__ W2,
                             const float* __restrict__ W3, const float* __restrict__ W4,
                             const int* __restrict__ nbr, int n_words)
{
    int b = blockIdx.x;
    int tid = threadIdx.x;

    if (b < 32) {
        // 8192 threads, each emits 8 contiguous k-halves for one (l, n)
        int t = b * 256 + tid;            // 0..8191
        int l = t >> 11;
        int rem = t & 2047;
        int n = rem >> 4;                 // 0..127
        int k0 = (rem & 15) << 3;         // 0,8,...,120
        const float* W = (l == 0) ? W1 : (l == 1) ? W2 : (l == 2) ? W3 : W4;
        __half h[8];
#pragma unroll
        for (int i = 0; i < 8; i++)
            h[i] = __float2half_rn(W[(k0 + i) * 128 + n]);   // W[k][n]
        *reinterpret_cast<uint4*>(&g_wh[l * (128 * AP) + n * AP + k0]) =
            *reinterpret_cast<uint4*>(h);
        return;
    }
    // dtype detection (block 32)
    __shared__ int any;
    if (tid == 0) any = 0;
    __syncthreads();
    int found = 0;
    for (int i = tid; i < 2048; i += blockDim.x) {
        int idx = 2 * i + 1;
        if (idx < n_words && nbr[idx] != 0) found = 1;
    }
    if (found) atomicOr(&any, 1);
    __syncthreads();
    if (tid == 0) g_is64 = (any == 0) ? 1 : 0;
}

// ---------------------------------------------------------------------------
// Edge pass: one warp = 4 edges, depth-2 prefetch on m_ji (MLP=2), PDL split.
// ---------------------------------------------------------------------------
__global__ void __launch_bounds__(256, 5) edge_kernel(
    const float* __restrict__ m_ji,
    const float* __restrict__ e_rbf,
    const int*   __restrict__ nbr,
    const float* __restrict__ W_edge,
    int E)
{
    __shared__ float sWe[6 * 128];
    int tid = threadIdx.x;
    for (int i = tid; i < 6 * 128; i += blockDim.x) sWe[i] = W_edge[i];
    __syncthreads();

    int warp = (int)((blockIdx.x * (long long)blockDim.x + tid) >> 5);
    int lane = tid & 31;
    long long e0 = (long long)warp * 4;
    if (e0 >= E) return;

    float rbf = 0.0f;
    if (lane < 24 && e0 * 6 + lane < (long long)E * 6)
        rbf = __ldcs(&e_rbf[e0 * 6 + lane]);

    const float4* we4 = reinterpret_cast<const float4*>(sWe);
    float4 wv[6];
#pragma unroll
    for (int r = 0; r < 6; r++) wv[r] = we4[r * 32 + lane];

    cudaGridDependencySynchronize();

    int is64 = g_is64;
    int d = 0;
    if (lane < 4 && e0 + lane < E)
        d = is64 ? __ldcs(&nbr[(e0 + lane) * 4 + 2]) : __ldcs(&nbr[(e0 + lane) * 2 + 1]);

    // depth-2 pipeline on m loads (per-warp MLP = 2)
    float4 mbuf[2];
    mbuf[0] = __ldcs(&reinterpret_cast<const float4*>(m_ji + e0 * EMB)[lane]);
    if (e0 + 1 < E)
        mbuf[1] = __ldcs(&reinterpret_cast<const float4*>(m_ji + (e0 + 1) * EMB)[lane]);

#pragma unroll
    for (int j = 0; j < 4; j++) {
        if (e0 + j >= E) break;
        float4 m = mbuf[j & 1];
        if (j + 2 < 4 && e0 + j + 2 < E)
            mbuf[j & 1] = __ldcs(&reinterpret_cast<const float4*>(m_ji + (e0 + j + 2) * EMB)[lane]);
        float4 w = make_float4(0.f, 0.f, 0.f, 0.f);
#pragma unroll
        for (int r = 0; r < 6; r++) {
            float c = __shfl_sync(0xffffffffu, rbf, j * 6 + r);
            w.x = fmaf(c, wv[r].x, w.x);
            w.y = fmaf(c, wv[r].y, w.y);
            w.z = fmaf(c, wv[r].z, w.z);
            w.w = fmaf(c, wv[r].w, w.w);
        }
        float4 o = make_float4(w.x * m.x, w.y * m.y, w.z * m.z, w.w * m.w);
        int dj = __shfl_sync(0xffffffffu, d, j);
        atomicAdd(reinterpret_cast<float4*>(&g_node[(long long)dj * EMB + lane * 4]), o);
    }
}

// ---------------------------------------------------------------------------
// MLP: pure fp16 mma.sync, 96 rows/CTA (6 m16 tiles), 2 CTAs/SM, 209 CTAs.
// A-init re-zeros g_node (streaming stores) to maintain the zero invariant.
// smem: A(26112) B(34816) bias(1536) = 62464 B per CTA
// ---------------------------------------------------------------------------
#define SA    0
#define SB    26112
#define SBIAS 60928
#define SMEM_TOTAL (60928 + 1536)
#define B_CHUNKS 2176               // 34816 B / 16 = float4 count for one buffer

__device__ __forceinline__ void issue_b_copy(uint32_t sb, int layer, int tid) {
    const char* src = reinterpret_cast<const char*>(g_wh + layer * (128 * AP));
#pragma unroll 4
    for (int i = tid; i < B_CHUNKS; i += 256)
        cp_async16(sb + SB + i * 16, src + i * 16);
    cp_async_commit();
}

template <int MT>
__device__ __forceinline__ void layer_compute(
    uint32_t aA, uint32_t bB,
    const int* tiles, float acc[][8][4])
{
#pragma unroll
    for (int mt = 0; mt < MT; mt++)
#pragma unroll
        for (int nt = 0; nt < 8; nt++)
#pragma unroll
            for (int q = 0; q < 4; q++) acc[mt][nt][q] = 0.0f;

#pragma unroll
    for (int k0 = 0; k0 < 128; k0 += 16) {
        uint32_t ah[MT][4];
#pragma unroll
        for (int mt = 0; mt < MT; mt++) {
            uint32_t toff = (uint32_t)(tiles[mt] * 16 * (AP * 2)) + k0 * 2;
            ldsm_x4(aA + toff, ah[mt]);
        }
#pragma unroll
        for (int nt2 = 0; nt2 < 4; nt2++) {
            uint32_t bh[4];
            ldsm_x4(bB + nt2 * 16 * (AP * 2) + k0 * 2, bh);
#pragma unroll
            for (int nt = 0; nt < 2; nt++) {
                int nti = nt2 * 2 + nt;
#pragma unroll
                for (int mt = 0; mt < MT; mt++)
                    mma16816h(acc[mt][nti], ah[mt], bh[nt * 2], bh[nt * 2 + 1]);
            }
        }
    }
}

template <int MT>
__device__ __forceinline__ void layer_epilogue_act(
    char* smem, const float* bia, const int* tiles, float acc[][8][4],
    int wcol, int g, int t2)
{
#pragma unroll
    for (int mt = 0; mt < MT; mt++) {
        int rA = tiles[mt] * 16 + g;
        int rB = rA + 8;
#pragma unroll
        for (int nt = 0; nt < 8; nt++) {
            int col = wcol * 64 + nt * 8 + t2;
            float b0 = bia[col], b1v = bia[col + 1];
            float s0 = fast_swish(acc[mt][nt][0] + b0);
            float s1 = fast_swish(acc[mt][nt][1] + b1v);
            float s2 = fast_swish(acc[mt][nt][2] + b0);
            float s3 = fast_swish(acc[mt][nt][3] + b1v);
            *reinterpret_cast<uint32_t*>(smem + SA + rA * (AP * 2) + col * 2) =
                pack_h2(s0, s1);
            *reinterpret_cast<uint32_t*>(smem + SA + rB * (AP * 2) + col * 2) =
                pack_h2(s2, s3);
        }
    }
}

template <int MT>
__device__ __forceinline__ void layer_epilogue_out(
    float* __restrict__ out, const int* tiles, float acc[][8][4],
    int row0, int natoms, int wcol, int g, int t2)
{
#pragma unroll
    for (int mt = 0; mt < MT; mt++) {
        int rA = row0 + tiles[mt] * 16 + g;
        int rB = rA + 8;
#pragma unroll
        for (int nt = 0; nt < 8; nt++) {
            int col = wcol * 64 + nt * 8 + t2;
            if (rA < natoms)
                *reinterpret_cast<float2*>(&out[(long long)rA * EMB + col]) =
                    make_float2(acc[mt][nt][0], acc[mt][nt][1]);
            if (rB < natoms)
                *reinterpret_cast<float2*>(&out[(long long)rB * EMB + col]) =
                    make_float2(acc[mt][nt][2], acc[mt][nt][3]);
        }
    }
}

__global__ void __launch_bounds__(256, 2) mlp_kernel(
    const float* __restrict__ b1, const float* __restrict__ b2,
    const float* __restrict__ b3,
    float* __restrict__ out, int natoms)
{
    extern __shared__ char smem[];
    uint32_t sb = smem_to_u32(smem);
    int tid = threadIdx.x;
    int wid = tid >> 5;
    int lane = tid & 31;
    int wrow = wid >> 1;              // 0..3
    int wcol = wid & 1;               // 0..1
    int row0 = blockIdx.x * MROWS;

    int tiles[2];
    tiles[0] = wrow;
    tiles[1] = wrow + 4;              // valid only for wrow<2
    bool has2 = (wrow < 2);

    // pre-sync prologue: layer-0 weight copy + biases
    issue_b_copy(sb, 0, tid);

    if (tid < 128) {
        float* bia = reinterpret_cast<float*>(smem + SBIAS);
        bia[tid] = b1[tid];
        bia[128 + tid] = b2[tid];
        bia[256 + tid] = b3[tid];
    }

    // wait for edge kernel's atomics into g_node
    cudaGridDependencySynchronize();

    // First-layer A: read g_node (streaming), convert to fp16, and re-zero
    // g_node so it is pristine for the next kernel_launch invocation.
    for (int i = tid; i < MROWS * 32; i += 256) {
        int r = i >> 5, c4 = i & 31;
        int gr = row0 + r;
        float4 v = make_float4(0.f, 0.f, 0.f, 0.f);
        if (gr < natoms) {
            float4* gp = &reinterpret_cast<float4*>(&g_node[(long long)gr * EMB])[c4];
            v = __ldcs(gp);
            __stcs(gp, make_float4(0.f, 0.f, 0.f, 0.f));
        }
        uint2 hp;
        hp.x = pack_h2(v.x, v.y);
        hp.y = pack_h2(v.z, v.w);
        *reinterpret_cast<uint2*>(smem + SA + r * (AP * 2) + c4 * 8) = hp;
    }

    uint32_t a_lane = (uint32_t)((lane & 15) * (AP * 2) + ((lane >> 4) * 8) * 2);
    uint32_t aA = sb + SA + a_lane;
    uint32_t b_row = (uint32_t)(((lane >> 4) & 1) * 8 + (lane & 7));
    uint32_t b_k   = (uint32_t)(((lane >> 3) & 1) * 8);
    uint32_t b_off = (uint32_t)((wcol * 64 + b_row) * (AP * 2) + b_k * 2);
    uint32_t bB = sb + SB + b_off;

    const float* bias_all = reinterpret_cast<const float*>(smem + SBIAS);
    int g = lane >> 2;
    int t2 = (lane & 3) * 2;

    float acc[2][8][4];

    cp_async_wait0();
    __syncthreads();   // A + B(0) visible to all warps

    for (int layer = 0; layer < 4; layer++) {
        if (has2) layer_compute<2>(aA, bB, tiles, acc);
        else      layer_compute<1>(aA, bB, tiles, acc);

        __syncthreads();   // all A and B reads done -> safe to overwrite both

        if (layer < 3) {
            issue_b_copy(sb, layer + 1, tid);
            const float* bia = bias_all + layer * 128;
            if (has2) layer_epilogue_act<2>(smem, bia, tiles, acc, wcol, g, t2);
            else      layer_epilogue_act<1>(smem, bia, tiles, acc, wcol, g, t2);
            cp_async_wait0();
            __syncthreads();   // A(next) + B(next) visible
        } else {
            if (has2) layer_epilogue_out<2>(out, tiles, acc, row0, natoms, wcol, g, t2);
            else      layer_epilogue_out<1>(out, tiles, acc, row0, natoms, wcol, g, t2);
        }
    }
}

// ---------------------------------------------------------------------------
extern "C" void kernel_launch(void* const* d_in, const int* in_sizes, int n_in,
                              void* d_out, int out_size)
{
    const float* m_ji  = (const float*)d_in[0];
    const float* e_rbf = (const float*)d_in[1];
    const int*   nbr   = (const int*)d_in[2];

    int base = (n_in >= 12 && in_sizes[3] < 16) ? 4 : 3;
    const float* W_edge = (const float*)d_in[base + 0];
    const float* W1 = (const float*)d_in[base + 1];
    const float* b1 = (const float*)d_in[base + 2];
    const float* W2 = (const float*)d_in[base + 3];
    const float* b2 = (const float*)d_in[base + 4];
    const float* W3 = (const float*)d_in[base + 5];
    const float* b3 = (const float*)d_in[base + 6];
    const float* W4 = (const float*)d_in[base + 7];

    int E = in_sizes[1] / 6;
    int natoms = out_size / EMB;
    if (natoms > MAX_ATOMS) natoms = MAX_ATOMS;
    float* out = (float*)d_out;

    // setup: weight prep + dtype detect (g_node already zero by invariant)
    setup_kernel<<<33, 256>>>(W1, W2, W3, W4, nbr, 2 * E);

    cudaLaunchAttribute pdl[1];
    pdl[0].id = cudaLaunchAttributeProgrammaticStreamSerialization;
    pdl[0].val.programmaticStreamSerializationAllowed = 1;

    // edge pass (PDL-dependent on setup)
    {
        int warps = (E + 3) / 4;
        int eblocks = (warps + 7) / 8;
        cudaLaunchConfig_t cfg = {};
        cfg.gridDim = dim3((unsigned)eblocks, 1, 1);
        cfg.blockDim = dim3(256, 1, 1);
        cfg.dynamicSmemBytes = 0;
        cfg.stream = 0;
        cfg.attrs = pdl;
        cfg.numAttrs = 1;
        cudaLaunchKernelEx(&cfg, edge_kernel, m_ji, e_rbf, nbr, W_edge, E);
    }

    // MLP (PDL-dependent on edge): 209 CTAs, 2 CTAs/SM, single wave
    cudaFuncSetAttribute(mlp_kernel, cudaFuncAttributeMaxDynamicSharedMemorySize, SMEM_TOTAL);
    {
        int mlp_blocks = (natoms + MROWS - 1) / MROWS;
        cudaLaunchConfig_t cfg = {};
        cfg.gridDim = dim3((unsigned)mlp_blocks, 1, 1);
        cfg.blockDim = dim3(256, 1, 1);
        cfg.dynamicSmemBytes = SMEM_TOTAL;
        cfg.stream = 0;
        cfg.attrs = pdl;
        cfg.numAttrs = 1;
        cudaLaunchKernelEx(&cfg, mlp_kernel, b1, b2, b3, out, natoms);
    }
}

// round 16
// speedup vs baseline: 1.1822x; 1.1822x over previous
#include <cuda_runtime.h>
#include <cuda_bf16.h>
#include <cuda_fp16.h>
#include <cstdint>

#define EMB 128
#define MAX_ATOMS 20000
#define AP 136                      // padded row stride (fp16 elems) = 272 B
#define MROWS 96                    // rows per MLP CTA (6 m16 tiles), 2 CTAs/SM

// ---------------------------------------------------------------------------
__device__ __align__(16) float g_node[MAX_ATOMS * EMB];     // segment-sum acc
__device__ __align__(16) __half g_wh[4 * 128 * AP];         // [layer][n*AP+k] fp16 weights
__device__ int g_is64;

// ---------------------------------------------------------------------------
__device__ __forceinline__ uint32_t smem_to_u32(const void* p) {
    uint32_t a;
    asm("{ .reg .u64 t; cvta.to.shared.u64 t, %1; cvt.u32.u64 %0, t; }" : "=r"(a) : "l"(p));
    return a;
}

__device__ __forceinline__ void ldsm_x4(uint32_t addr, uint32_t r[4]) {
    asm volatile("ldmatrix.sync.aligned.m8n8.x4.shared.b16 {%0,%1,%2,%3}, [%4];"
                 : "=r"(r[0]), "=r"(r[1]), "=r"(r[2]), "=r"(r[3]) : "r"(addr));
}

__device__ __forceinline__ void mma16816h(float d[4], const uint32_t a[4],
                                          uint32_t b0, uint32_t b1) {
    asm volatile(
        "mma.sync.aligned.m16n8k16.row.col.f32.f16.f16.f32 "
        "{%0,%1,%2,%3}, {%4,%5,%6,%7}, {%8,%9}, {%0,%1,%2,%3};"
        : "+f"(d[0]), "+f"(d[1]), "+f"(d[2]), "+f"(d[3])
        : "r"(a[0]), "r"(a[1]), "r"(a[2]), "r"(a[3]), "r"(b0), "r"(b1));
}

__device__ __forceinline__ uint32_t pack_h2(float x, float y) {
    __half2 v;
    v.x = __float2half_rn(x);
    v.y = __float2half_rn(y);
    return *reinterpret_cast<uint32_t*>(&v);
}

__device__ __forceinline__ void cp_async16(uint32_t smem_addr, const void* gptr) {
    asm volatile("cp.async.cg.shared.global [%0], [%1], 16;"
                 :: "r"(smem_addr), "l"(gptr));
}
__device__ __forceinline__ void cp_async_commit() {
    asm volatile("cp.async.commit_group;" ::: "memory");
}
__device__ __forceinline__ void cp_async_wait0() {
    asm volatile("cp.async.wait_group 0;" ::: "memory");
}

// fast swish: x * sigmoid(x) via EX2 + RCP (no IEEE div)
__device__ __forceinline__ float fast_swish(float x) {
    float e = __expf(-x);
    return __fdividef(x, 1.0f + e);
}

// ---------------------------------------------------------------------------
// Fused setup (257 blocks):
//   blocks 0..255 : grid-stride zero of g_node (also L2-warms the atomic
//                   target); blocks 0..31 ALSO do weight prep with coalesced
//                   16B writes (8 k-halves per thread)
//   block  256    : dtype detect
// ---------------------------------------------------------------------------
__global__ void setup_kernel(const float* __restrict__ W1, const float* __restrict__ W2,
                             const float* __restrict__ W3, const float* __restrict__ W4,
                             const int* __restrict__ nbr, int n_words, int n4)
{
    int b = blockIdx.x;
    int tid = threadIdx.x;

    if (b < 256) {
        float4* gz = reinterpret_cast<float4*>(g_node);
        for (int i = b * 256 + tid; i < n4; i += 256 * 256)
            gz[i] = make_float4(0.f, 0.f, 0.f, 0.f);

        if (b < 32) {
            // 8192 threads, each emits 8 contiguous k-halves for one (l, n)
            int t = b * 256 + tid;            // 0..8191
            int l = t >> 11;
            int rem = t & 2047;
            int n = rem >> 4;                 // 0..127
            int k0 = (rem & 15) << 3;         // 0,8,...,120
            const float* W = (l == 0) ? W1 : (l == 1) ? W2 : (l == 2) ? W3 : W4;
            __half h[8];
#pragma unroll
            for (int i = 0; i < 8; i++)
                h[i] = __float2half_rn(W[(k0 + i) * 128 + n]);   // W[k][n]
            *reinterpret_cast<uint4*>(&g_wh[l * (128 * AP) + n * AP + k0]) =
                *reinterpret_cast<uint4*>(h);
        }
        return;
    }
    // dtype detection (block 256)
    __shared__ int any;
    if (tid == 0) any = 0;
    __syncthreads();
    int found = 0;
    for (int i = tid; i < 2048; i += blockDim.x) {
        int idx = 2 * i + 1;
        if (idx < n_words && nbr[idx] != 0) found = 1;
    }
    if (found) atomicOr(&any, 1);
    __syncthreads();
    if (tid == 0) g_is64 = (any == 0) ? 1 : 0;
}

// ---------------------------------------------------------------------------
// Edge pass: one warp = 4 edges, depth-2 prefetch on m_ji (MLP=2), PDL split.
// ---------------------------------------------------------------------------
__global__ void __launch_bounds__(256, 5) edge_kernel(
    const float* __restrict__ m_ji,
    const float* __restrict__ e_rbf,
    const int*   __restrict__ nbr,
    const float* __restrict__ W_edge,
    int E)
{
    __shared__ float sWe[6 * 128];
    int tid = threadIdx.x;
    for (int i = tid; i < 6 * 128; i += blockDim.x) sWe[i] = W_edge[i];
    __syncthreads();

    int warp = (int)((blockIdx.x * (long long)blockDim.x + tid) >> 5);
    int lane = tid & 31;
    long long e0 = (long long)warp * 4;
    if (e0 >= E) return;

    float rbf = 0.0f;
    if (lane < 24 && e0 * 6 + lane < (long long)E * 6)
        rbf = __ldcs(&e_rbf[e0 * 6 + lane]);

    const float4* we4 = reinterpret_cast<const float4*>(sWe);
    float4 wv[6];
#pragma unroll
    for (int r = 0; r < 6; r++) wv[r] = we4[r * 32 + lane];

    cudaGridDependencySynchronize();

    int is64 = g_is64;
    int d = 0;
    if (lane < 4 && e0 + lane < E)
        d = is64 ? __ldcs(&nbr[(e0 + lane) * 4 + 2]) : __ldcs(&nbr[(e0 + lane) * 2 + 1]);

    // depth-2 pipeline on m loads (per-warp MLP = 2)
    float4 mbuf[2];
    mbuf[0] = __ldcs(&reinterpret_cast<const float4*>(m_ji + e0 * EMB)[lane]);
    if (e0 + 1 < E)
        mbuf[1] = __ldcs(&reinterpret_cast<const float4*>(m_ji + (e0 + 1) * EMB)[lane]);

#pragma unroll
    for (int j = 0; j < 4; j++) {
        if (e0 + j >= E) break;
        float4 m = mbuf[j & 1];
        if (j + 2 < 4 && e0 + j + 2 < E)
            mbuf[j & 1] = __ldcs(&reinterpret_cast<const float4*>(m_ji + (e0 + j + 2) * EMB)[lane]);
        float4 w = make_float4(0.f, 0.f, 0.f, 0.f);
#pragma unroll
        for (int r = 0; r < 6; r++) {
            float c = __shfl_sync(0xffffffffu, rbf, j * 6 + r);
            w.x = fmaf(c, wv[r].x, w.x);
            w.y = fmaf(c, wv[r].y, w.y);
            w.z = fmaf(c, wv[r].z, w.z);
            w.w = fmaf(c, wv[r].w, w.w);
        }
        float4 o = make_float4(w.x * m.x, w.y * m.y, w.z * m.z, w.w * m.w);
        int dj = __shfl_sync(0xffffffffu, d, j);
        atomicAdd(reinterpret_cast<float4*>(&g_node[(long long)dj * EMB + lane * 4]), o);
    }
}

// ---------------------------------------------------------------------------
// MLP: pure fp16 mma.sync, 96 rows/CTA (6 m16 tiles), 2 CTAs/SM, 209 CTAs.
// smem: A(26112) B(34816) bias(1536) = 62464 B per CTA
// ---------------------------------------------------------------------------
#define SA    0
#define SB    26112
#define SBIAS 60928
#define SMEM_TOTAL (60928 + 1536)
#define B_CHUNKS 2176               // 34816 B / 16 = float4 count for one buffer

__device__ __forceinline__ void issue_b_copy(uint32_t sb, int layer, int tid) {
    const char* src = reinterpret_cast<const char*>(g_wh + layer * (128 * AP));
#pragma unroll 4
    for (int i = tid; i < B_CHUNKS; i += 256)
        cp_async16(sb + SB + i * 16, src + i * 16);
    cp_async_commit();
}

template <int MT>
__device__ __forceinline__ void layer_compute(
    uint32_t aA, uint32_t bB,
    const int* tiles, float acc[][8][4])
{
#pragma unroll
    for (int mt = 0; mt < MT; mt++)
#pragma unroll
        for (int nt = 0; nt < 8; nt++)
#pragma unroll
            for (int q = 0; q < 4; q++) acc[mt][nt][q] = 0.0f;

#pragma unroll
    for (int k0 = 0; k0 < 128; k0 += 16) {
        uint32_t ah[MT][4];
#pragma unroll
        for (int mt = 0; mt < MT; mt++) {
            uint32_t toff = (uint32_t)(tiles[mt] * 16 * (AP * 2)) + k0 * 2;
            ldsm_x4(aA + toff, ah[mt]);
        }
#pragma unroll
        for (int nt2 = 0; nt2 < 4; nt2++) {
            uint32_t bh[4];
            ldsm_x4(bB + nt2 * 16 * (AP * 2) + k0 * 2, bh);
#pragma unroll
            for (int nt = 0; nt < 2; nt++) {
                int nti = nt2 * 2 + nt;
#pragma unroll
                for (int mt = 0; mt < MT; mt++)
                    mma16816h(acc[mt][nti], ah[mt], bh[nt * 2], bh[nt * 2 + 1]);
            }
        }
    }
}

template <int MT>
__device__ __forceinline__ void layer_epilogue_act(
    char* smem, const float* bia, const int* tiles, float acc[][8][4],
    int wcol, int g, int t2)
{
#pragma unroll
    for (int mt = 0; mt < MT; mt++) {
        int rA = tiles[mt] * 16 + g;
        int rB = rA + 8;
#pragma unroll
        for (int nt = 0; nt < 8; nt++) {
            int col = wcol * 64 + nt * 8 + t2;
            float b0 = bia[col], b1v = bia[col + 1];
            float s0 = fast_swish(acc[mt][nt][0] + b0);
            float s1 = fast_swish(acc[mt][nt][1] + b1v);
            float s2 = fast_swish(acc[mt][nt][2] + b0);
            float s3 = fast_swish(acc[mt][nt][3] + b1v);
            *reinterpret_cast<uint32_t*>(smem + SA + rA * (AP * 2) + col * 2) =
                pack_h2(s0, s1);
            *reinterpret_cast<uint32_t*>(smem + SA + rB * (AP * 2) + col * 2) =
                pack_h2(s2, s3);
        }
    }
}

template <int MT>
__device__ __forceinline__ void layer_epilogue_out(
    float* __restrict__ out, const int* tiles, float acc[][8][4],
    int row0, int natoms, int wcol, int g, int t2)
{
#pragma unroll
    for (int mt = 0; mt < MT; mt++) {
        int rA = row0 + tiles[mt] * 16 + g;
        int rB = rA + 8;
#pragma unroll
        for (int nt = 0; nt < 8; nt++) {
            int col = wcol * 64 + nt * 8 + t2;
            if (rA < natoms)
                *reinterpret_cast<float2*>(&out[(long long)rA * EMB + col]) =
                    make_float2(acc[mt][nt][0], acc[mt][nt][1]);
            if (rB < natoms)
                *reinterpret_cast<float2*>(&out[(long long)rB * EMB + col]) =
                    make_float2(acc[mt][nt][2], acc[mt][nt][3]);
        }
    }
}

__global__ void __launch_bounds__(256, 2) mlp_kernel(
    const float* __restrict__ b1, const float* __restrict__ b2,
    const float* __restrict__ b3,
    float* __restrict__ out, int natoms)
{
    extern __shared__ char smem[];
    uint32_t sb = smem_to_u32(smem);
    int tid = threadIdx.x;
    int wid = tid >> 5;
    int lane = tid & 31;
    int wrow = wid >> 1;              // 0..3
    int wcol = wid & 1;               // 0..1
    int row0 = blockIdx.x * MROWS;

    int tiles[2];
    tiles[0] = wrow;
    tiles[1] = wrow + 4;              // valid only for wrow<2
    bool has2 = (wrow < 2);

    // pre-sync prologue: layer-0 weight copy + biases
    issue_b_copy(sb, 0, tid);

    if (tid < 128) {
        float* bia = reinterpret_cast<float*>(smem + SBIAS);
        bia[tid] = b1[tid];
        bia[128 + tid] = b2[tid];
        bia[256 + tid] = b3[tid];
    }

    // wait for edge kernel's atomics into g_node
    cudaGridDependencySynchronize();

    // First-layer A: fp32 g_node -> fp16, padded [row][k] layout.
    for (int i = tid; i < MROWS * 32; i += 256) {
        int r = i >> 5, c4 = i & 31;
        int gr = row0 + r;
        float4 v = make_float4(0.f, 0.f, 0.f, 0.f);
        if (gr < natoms)
            v = __ldcs(&reinterpret_cast<const float4*>(&g_node[(long long)gr * EMB])[c4]);
        uint2 hp;
        hp.x = pack_h2(v.x, v.y);
        hp.y = pack_h2(v.z, v.w);
        *reinterpret_cast<uint2*>(smem + SA + r * (AP * 2) + c4 * 8) = hp;
    }

    uint32_t a_lane = (uint32_t)((lane & 15) * (AP * 2) + ((lane >> 4) * 8) * 2);
    uint32_t aA = sb + SA + a_lane;
    uint32_t b_row = (uint32_t)(((lane >> 4) & 1) * 8 + (lane & 7));
    uint32_t b_k   = (uint32_t)(((lane >> 3) & 1) * 8);
    uint32_t b_off = (uint32_t)((wcol * 64 + b_row) * (AP * 2) + b_k * 2);
    uint32_t bB = sb + SB + b_off;

    const float* bias_all = reinterpret_cast<const float*>(smem + SBIAS);
    int g = lane >> 2;
    int t2 = (lane & 3) * 2;

    float acc[2][8][4];

    cp_async_wait0();
    __syncthreads();   // A + B(0) visible to all warps

    for (int layer = 0; layer < 4; layer++) {
        if (has2) layer_compute<2>(aA, bB, tiles, acc);
        else      layer_compute<1>(aA, bB, tiles, acc);

        __syncthreads();   // all A and B reads done -> safe to overwrite both

        if (layer < 3) {
            issue_b_copy(sb, layer + 1, tid);
            const float* bia = bias_all + layer * 128;
            if (has2) layer_epilogue_act<2>(smem, bia, tiles, acc, wcol, g, t2);
            else      layer_epilogue_act<1>(smem, bia, tiles, acc, wcol, g, t2);
            cp_async_wait0();
            __syncthreads();   // A(next) + B(next) visible
        } else {
            if (has2) layer_epilogue_out<2>(out, tiles, acc, row0, natoms, wcol, g, t2);
            else      layer_epilogue_out<1>(out, tiles, acc, row0, natoms, wcol, g, t2);
        }
    }
}

// ---------------------------------------------------------------------------
extern "C" void kernel_launch(void* const* d_in, const int* in_sizes, int n_in,
                              void* d_out, int out_size)
{
    const float* m_ji  = (const float*)d_in[0];
    const float* e_rbf = (const float*)d_in[1];
    const int*   nbr   = (const int*)d_in[2];

    int base = (n_in >= 12 && in_sizes[3] < 16) ? 4 : 3;
    const float* W_edge = (const float*)d_in[base + 0];
    const float* W1 = (const float*)d_in[base + 1];
    const float* b1 = (const float*)d_in[base + 2];
    const float* W2 = (const float*)d_in[base + 3];
    const float* b2 = (const float*)d_in[base + 4];
    const float* W3 = (const float*)d_in[base + 5];
    const float* b3 = (const float*)d_in[base + 6];
    const float* W4 = (const float*)d_in[base + 7];

    int E = in_sizes[1] / 6;
    int natoms = out_size / EMB;
    if (natoms > MAX_ATOMS) natoms = MAX_ATOMS;
    float* out = (float*)d_out;

    // setup: zero (L2-warm) + coalesced weight prep + dtype detect
    int n4 = natoms * EMB / 4;
    setup_kernel<<<257, 256>>>(W1, W2, W3, W4, nbr, 2 * E, n4);

    cudaLaunchAttribute pdl[1];
    pdl[0].id = cudaLaunchAttributeProgrammaticStreamSerialization;
    pdl[0].val.programmaticStreamSerializationAllowed = 1;

    // edge pass (PDL-dependent on setup)
    {
        int warps = (E + 3) / 4;
        int eblocks = (warps + 7) / 8;
        cudaLaunchConfig_t cfg = {};
        cfg.gridDim = dim3((unsigned)eblocks, 1, 1);
        cfg.blockDim = dim3(256, 1, 1);
        cfg.dynamicSmemBytes = 0;
        cfg.stream = 0;
        cfg.attrs = pdl;
        cfg.numAttrs = 1;
        cudaLaunchKernelEx(&cfg, edge_kernel, m_ji, e_rbf, nbr, W_edge, E);
    }

    // MLP (PDL-dependent on edge): 209 CTAs, 2 CTAs/SM, single wave
    cudaFuncSetAttribute(mlp_kernel, cudaFuncAttributeMaxDynamicSharedMemorySize, SMEM_TOTAL);
    {
        int mlp_blocks = (natoms + MROWS - 1) / MROWS;
        cudaLaunchConfig_t cfg = {};
        cfg.gridDim = dim3((unsigned)mlp_blocks, 1, 1);
        cfg.blockDim = dim3(256, 1, 1);
        cfg.dynamicSmemBytes = SMEM_TOTAL;
        cfg.stream = 0;
        cfg.attrs = pdl;
        cfg.numAttrs = 1;
        cudaLaunchKernelEx(&cfg, mlp_kernel, b1, b2, b3, out, natoms);
    }
}

// round 17
// speedup vs baseline: 1.1916x; 1.0079x over previous
#include <cuda_runtime.h>
#include <cuda_bf16.h>
#include <cuda_fp16.h>
#include <cstdint>

#define EMB 128
#define MAX_ATOMS 20000
#define AP 136                      // padded row stride (fp16 elems) = 272 B
#define MROWS 96                    // rows per MLP CTA (6 m16 tiles), 2 CTAs/SM

// ---------------------------------------------------------------------------
__device__ __align__(16) float g_node[MAX_ATOMS * EMB];     // segment-sum acc
__device__ __align__(16) __half g_wh[4 * 128 * AP];         // [layer][n*AP+k] fp16 weights
__device__ int g_is64;

// ---------------------------------------------------------------------------
__device__ __forceinline__ uint32_t smem_to_u32(const void* p) {
    uint32_t a;
    asm("{ .reg .u64 t; cvta.to.shared.u64 t, %1; cvt.u32.u64 %0, t; }" : "=r"(a) : "l"(p));
    return a;
}

__device__ __forceinline__ void ldsm_x4(uint32_t addr, uint32_t r[4]) {
    asm volatile("ldmatrix.sync.aligned.m8n8.x4.shared.b16 {%0,%1,%2,%3}, [%4];"
                 : "=r"(r[0]), "=r"(r[1]), "=r"(r[2]), "=r"(r[3]) : "r"(addr));
}

__device__ __forceinline__ void mma16816h(float d[4], const uint32_t a[4],
                                          uint32_t b0, uint32_t b1) {
    asm volatile(
        "mma.sync.aligned.m16n8k16.row.col.f32.f16.f16.f32 "
        "{%0,%1,%2,%3}, {%4,%5,%6,%7}, {%8,%9}, {%0,%1,%2,%3};"
        : "+f"(d[0]), "+f"(d[1]), "+f"(d[2]), "+f"(d[3])
        : "r"(a[0]), "r"(a[1]), "r"(a[2]), "r"(a[3]), "r"(b0), "r"(b1));
}

__device__ __forceinline__ uint32_t pack_h2(float x, float y) {
    __half2 v;
    v.x = __float2half_rn(x);
    v.y = __float2half_rn(y);
    return *reinterpret_cast<uint32_t*>(&v);
}

__device__ __forceinline__ void cp_async16(uint32_t smem_addr, const void* gptr) {
    asm volatile("cp.async.cg.shared.global [%0], [%1], 16;"
                 :: "r"(smem_addr), "l"(gptr));
}
__device__ __forceinline__ void cp_async_commit() {
    asm volatile("cp.async.commit_group;" ::: "memory");
}
__device__ __forceinline__ void cp_async_wait0() {
    asm volatile("cp.async.wait_group 0;" ::: "memory");
}

// fast swish via tanh: swish(x) = 0.5x + 0.5x*tanh(x/2). 1 MUFU + 3 FMA.
__device__ __forceinline__ float fast_swish(float x) {
    float t;
    asm("tanh.approx.f32 %0, %1;" : "=f"(t) : "f"(0.5f * x));
    float hx = 0.5f * x;
    return fmaf(hx, t, hx);
}

// ---------------------------------------------------------------------------
// Fused setup (257 blocks):
//   blocks 0..255 : grid-stride zero of g_node (also L2-warms the atomic
//                   target); blocks 0..31 ALSO do weight prep with coalesced
//                   16B writes (8 k-halves per thread)
//   block  256    : dtype detect
// ---------------------------------------------------------------------------
__global__ void setup_kernel(const float* __restrict__ W1, const float* __restrict__ W2,
                             const float* __restrict__ W3, const float* __restrict__ W4,
                             const int* __restrict__ nbr, int n_words, int n4)
{
    int b = blockIdx.x;
    int tid = threadIdx.x;

    if (b < 256) {
        float4* gz = reinterpret_cast<float4*>(g_node);
        for (int i = b * 256 + tid; i < n4; i += 256 * 256)
            gz[i] = make_float4(0.f, 0.f, 0.f, 0.f);

        if (b < 32) {
            int t = b * 256 + tid;            // 0..8191
            int l = t >> 11;
            int rem = t & 2047;
            int n = rem >> 4;                 // 0..127
            int k0 = (rem & 15) << 3;         // 0,8,...,120
            const float* W = (l == 0) ? W1 : (l == 1) ? W2 : (l == 2) ? W3 : W4;
            __half h[8];
#pragma unroll
            for (int i = 0; i < 8; i++)
                h[i] = __float2half_rn(W[(k0 + i) * 128 + n]);   // W[k][n]
            *reinterpret_cast<uint4*>(&g_wh[l * (128 * AP) + n * AP + k0]) =
                *reinterpret_cast<uint4*>(h);
        }
        return;
    }
    // dtype detection (block 256)
    __shared__ int any;
    if (tid == 0) any = 0;
    __syncthreads();
    int found = 0;
    for (int i = tid; i < 2048; i += blockDim.x) {
        int idx = 2 * i + 1;
        if (idx < n_words && nbr[idx] != 0) found = 1;
    }
    if (found) atomicOr(&any, 1);
    __syncthreads();
    if (tid == 0) g_is64 = (any == 0) ? 1 : 0;
}

// ---------------------------------------------------------------------------
// Edge pass: one warp = 4 edges, depth-2 prefetch on m_ji (MLP=2), PDL split.
// ---------------------------------------------------------------------------
__global__ void __launch_bounds__(256, 5) edge_kernel(
    const float* __restrict__ m_ji,
    const float* __restrict__ e_rbf,
    const int*   __restrict__ nbr,
    const float* __restrict__ W_edge,
    int E)
{
    __shared__ float sWe[6 * 128];
    int tid = threadIdx.x;
    for (int i = tid; i < 6 * 128; i += blockDim.x) sWe[i] = W_edge[i];
    __syncthreads();

    int warp = (int)((blockIdx.x * (long long)blockDim.x + tid) >> 5);
    int lane = tid & 31;
    long long e0 = (long long)warp * 4;
    if (e0 >= E) return;

    float rbf = 0.0f;
    if (lane < 24 && e0 * 6 + lane < (long long)E * 6)
        rbf = __ldcs(&e_rbf[e0 * 6 + lane]);

    const float4* we4 = reinterpret_cast<const float4*>(sWe);
    float4 wv[6];
#pragma unroll
    for (int r = 0; r < 6; r++) wv[r] = we4[r * 32 + lane];

    cudaGridDependencySynchronize();

    int is64 = g_is64;
    int d = 0;
    if (lane < 4 && e0 + lane < E)
        d = is64 ? __ldcs(&nbr[(e0 + lane) * 4 + 2]) : __ldcs(&nbr[(e0 + lane) * 2 + 1]);

    // depth-2 pipeline on m loads (per-warp MLP = 2)
    float4 mbuf[2];
    mbuf[0] = __ldcs(&reinterpret_cast<const float4*>(m_ji + e0 * EMB)[lane]);
    if (e0 + 1 < E)
        mbuf[1] = __ldcs(&reinterpret_cast<const float4*>(m_ji + (e0 + 1) * EMB)[lane]);

#pragma unroll
    for (int j = 0; j < 4; j++) {
        if (e0 + j >= E) break;
        float4 m = mbuf[j & 1];
        if (j + 2 < 4 && e0 + j + 2 < E)
            mbuf[j & 1] = __ldcs(&reinterpret_cast<const float4*>(m_ji + (e0 + j + 2) * EMB)[lane]);
        float4 w = make_float4(0.f, 0.f, 0.f, 0.f);
#pragma unroll
        for (int r = 0; r < 6; r++) {
            float c = __shfl_sync(0xffffffffu, rbf, j * 6 + r);
            w.x = fmaf(c, wv[r].x, w.x);
            w.y = fmaf(c, wv[r].y, w.y);
            w.z = fmaf(c, wv[r].z, w.z);
            w.w = fmaf(c, wv[r].w, w.w);
        }
        float4 o = make_float4(w.x * m.x, w.y * m.y, w.z * m.z, w.w * m.w);
        int dj = __shfl_sync(0xffffffffu, d, j);
        atomicAdd(reinterpret_cast<float4*>(&g_node[(long long)dj * EMB + lane * 4]), o);
    }
}

// ---------------------------------------------------------------------------
// MLP: pure fp16 mma.sync, 96 rows/CTA (6 m16 tiles), 2 CTAs/SM, 209 CTAs.
// smem: A(26112) B(34816) bias(1536) = 62464 B per CTA
// ---------------------------------------------------------------------------
#define SA    0
#define SB    26112
#define SBIAS 60928
#define SMEM_TOTAL (60928 + 1536)
#define B_CHUNKS 2176               // 34816 B / 16 = float4 count for one buffer

__device__ __forceinline__ void issue_b_copy(uint32_t sb, int layer, int tid) {
    const char* src = reinterpret_cast<const char*>(g_wh + layer * (128 * AP));
#pragma unroll 4
    for (int i = tid; i < B_CHUNKS; i += 256)
        cp_async16(sb + SB + i * 16, src + i * 16);
    cp_async_commit();
}

template <int MT>
__device__ __forceinline__ void layer_compute(
    uint32_t aA, uint32_t bB,
    const int* tiles, float acc[][8][4])
{
#pragma unroll
    for (int mt = 0; mt < MT; mt++)
#pragma unroll
        for (int nt = 0; nt < 8; nt++)
#pragma unroll
            for (int q = 0; q < 4; q++) acc[mt][nt][q] = 0.0f;

#pragma unroll
    for (int k0 = 0; k0 < 128; k0 += 16) {
        uint32_t ah[MT][4];
#pragma unroll
        for (int mt = 0; mt < MT; mt++) {
            uint32_t toff = (uint32_t)(tiles[mt] * 16 * (AP * 2)) + k0 * 2;
            ldsm_x4(aA + toff, ah[mt]);
        }
#pragma unroll
        for (int nt2 = 0; nt2 < 4; nt2++) {
            uint32_t bh[4];
            ldsm_x4(bB + nt2 * 16 * (AP * 2) + k0 * 2, bh);
#pragma unroll
            for (int nt = 0; nt < 2; nt++) {
                int nti = nt2 * 2 + nt;
#pragma unroll
                for (int mt = 0; mt < MT; mt++)
                    mma16816h(acc[mt][nti], ah[mt], bh[nt * 2], bh[nt * 2 + 1]);
            }
        }
    }
}

template <int MT>
__device__ __forceinline__ void layer_epilogue_act(
    char* smem, const float* bia, const int* tiles, float acc[][8][4],
    int wcol, int g, int t2)
{
#pragma unroll
    for (int mt = 0; mt < MT; mt++) {
        int rA = tiles[mt] * 16 + g;
        int rB = rA + 8;
#pragma unroll
        for (int nt = 0; nt < 8; nt++) {
            int col = wcol * 64 + nt * 8 + t2;
            float b0 = bia[col], b1v = bia[col + 1];
            float s0 = fast_swish(acc[mt][nt][0] + b0);
            float s1 = fast_swish(acc[mt][nt][1] + b1v);
            float s2 = fast_swish(acc[mt][nt][2] + b0);
            float s3 = fast_swish(acc[mt][nt][3] + b1v);
            *reinterpret_cast<uint32_t*>(smem + SA + rA * (AP * 2) + col * 2) =
                pack_h2(s0, s1);
            *reinterpret_cast<uint32_t*>(smem + SA + rB * (AP * 2) + col * 2) =
                pack_h2(s2, s3);
        }
    }
}

template <int MT>
__device__ __forceinline__ void layer_epilogue_out(
    float* __restrict__ out, const int* tiles, float acc[][8][4],
    int row0, int natoms, int wcol, int g, int t2)
{
#pragma unroll
    for (int mt = 0; mt < MT; mt++) {
        int rA = row0 + tiles[mt] * 16 + g;
        int rB = rA + 8;
#pragma unroll
        for (int nt = 0; nt < 8; nt++) {
            int col = wcol * 64 + nt * 8 + t2;
            if (rA < natoms)
                *reinterpret_cast<float2*>(&out[(long long)rA * EMB + col]) =
                    make_float2(acc[mt][nt][0], acc[mt][nt][1]);
            if (rB < natoms)
                *reinterpret_cast<float2*>(&out[(long long)rB * EMB + col]) =
                    make_float2(acc[mt][nt][2], acc[mt][nt][3]);
        }
    }
}

__global__ void __launch_bounds__(256, 2) mlp_kernel(
    const float* __restrict__ b1, const float* __restrict__ b2,
    const float* __restrict__ b3,
    float* __restrict__ out, int natoms)
{
    extern __shared__ char smem[];
    uint32_t sb = smem_to_u32(smem);
    int tid = threadIdx.x;
    int wid = tid >> 5;
    int lane = tid & 31;
    int wrow = wid >> 1;              // 0..3
    int wcol = wid & 1;               // 0..1
    int row0 = blockIdx.x * MROWS;

    int tiles[2];
    tiles[0] = wrow;
    tiles[1] = wrow + 4;              // valid only for wrow<2
    bool has2 = (wrow < 2);

    // pre-sync prologue: layer-0 weight copy + biases
    issue_b_copy(sb, 0, tid);

    if (tid < 128) {
        float* bia = reinterpret_cast<float*>(smem + SBIAS);
        bia[tid] = b1[tid];
        bia[128 + tid] = b2[tid];
        bia[256 + tid] = b3[tid];
    }

    // wait for edge kernel's atomics into g_node
    cudaGridDependencySynchronize();

    // First-layer A: fp32 g_node -> fp16, padded [row][k] layout.
    for (int i = tid; i < MROWS * 32; i += 256) {
        int r = i >> 5, c4 = i & 31;
        int gr = row0 + r;
        float4 v = make_float4(0.f, 0.f, 0.f, 0.f);
        if (gr < natoms)
            v = __ldcs(&reinterpret_cast<const float4*>(&g_node[(long long)gr * EMB])[c4]);
        uint2 hp;
        hp.x = pack_h2(v.x, v.y);
        hp.y = pack_h2(v.z, v.w);
        *reinterpret_cast<uint2*>(smem + SA + r * (AP * 2) + c4 * 8) = hp;
    }

    uint32_t a_lane = (uint32_t)((lane & 15) * (AP * 2) + ((lane >> 4) * 8) * 2);
    uint32_t aA = sb + SA + a_lane;
    uint32_t b_row = (uint32_t)(((lane >> 4) & 1) * 8 + (lane & 7));
    uint32_t b_k   = (uint32_t)(((lane >> 3) & 1) * 8);
    uint32_t b_off = (uint32_t)((wcol * 64 + b_row) * (AP * 2) + b_k * 2);
    uint32_t bB = sb + SB + b_off;

    const float* bias_all = reinterpret_cast<const float*>(smem + SBIAS);
    int g = lane >> 2;
    int t2 = (lane & 3) * 2;

    float acc[2][8][4];

    cp_async_wait0();
    __syncthreads();   // A + B(0) visible to all warps

    for (int layer = 0; layer < 4; layer++) {
        if (has2) layer_compute<2>(aA, bB, tiles, acc);
        else      layer_compute<1>(aA, bB, tiles, acc);

        __syncthreads();   // all A and B reads done -> safe to overwrite both

        if (layer < 3) {
            issue_b_copy(sb, layer + 1, tid);
            const float* bia = bias_all + layer * 128;
            if (has2) layer_epilogue_act<2>(smem, bia, tiles, acc, wcol, g, t2);
            else      layer_epilogue_act<1>(smem, bia, tiles, acc, wcol, g, t2);
            cp_async_wait0();
            __syncthreads();   // A(next) + B(next) visible
        } else {
            if (has2) layer_epilogue_out<2>(out, tiles, acc, row0, natoms, wcol, g, t2);
            else      layer_epilogue_out<1>(out, tiles, acc, row0, natoms, wcol, g, t2);
        }
    }
}

// ---------------------------------------------------------------------------
extern "C" void kernel_launch(void* const* d_in, const int* in_sizes, int n_in,
                              void* d_out, int out_size)
{
    const float* m_ji  = (const float*)d_in[0];
    const float* e_rbf = (const float*)d_in[1];
    const int*   nbr   = (const int*)d_in[2];

    int base = (n_in >= 12 && in_sizes[3] < 16) ? 4 : 3;
    const float* W_edge = (const float*)d_in[base + 0];
    const float* W1 = (const float*)d_in[base + 1];
    const float* b1 = (const float*)d_in[base + 2];
    const float* W2 = (const float*)d_in[base + 3];
    const float* b2 = (const float*)d_in[base + 4];
    const float* W3 = (const float*)d_in[base + 5];
    const float* b3 = (const float*)d_in[base + 6];
    const float* W4 = (const float*)d_in[base + 7];

    int E = in_sizes[1] / 6;
    int natoms = out_size / EMB;
    if (natoms > MAX_ATOMS) natoms = MAX_ATOMS;
    float* out = (float*)d_out;

    // setup: zero (L2-warm) + coalesced weight prep + dtype detect
    int n4 = natoms * EMB / 4;
    setup_kernel<<<257, 256>>>(W1, W2, W3, W4, nbr, 2 * E, n4);

    cudaLaunchAttribute pdl[1];
    pdl[0].id = cudaLaunchAttributeProgrammaticStreamSerialization;
    pdl[0].val.programmaticStreamSerializationAllowed = 1;

    // edge pass (PDL-dependent on setup)
    {
        int warps = (E + 3) / 4;
        int eblocks = (warps + 7) / 8;
        cudaLaunchConfig_t cfg = {};
        cfg.gridDim = dim3((unsigned)eblocks, 1, 1);
        cfg.blockDim = dim3(256, 1, 1);
        cfg.dynamicSmemBytes = 0;
        cfg.stream = 0;
        cfg.attrs = pdl;
        cfg.numAttrs = 1;
        cudaLaunchKernelEx(&cfg, edge_kernel, m_ji, e_rbf, nbr, W_edge, E);
    }

    // MLP (PDL-dependent on edge): 209 CTAs, 2 CTAs/SM, single wave
    cudaFuncSetAttribute(mlp_kernel, cudaFuncAttributeMaxDynamicSharedMemorySize, SMEM_TOTAL);
    {
        int mlp_blocks = (natoms + MROWS - 1) / MROWS;
        cudaLaunchConfig_t cfg = {};
        cfg.gridDim = dim3((unsigned)mlp_blocks, 1, 1);
        cfg.blockDim = dim3(256, 1, 1);
        cfg.dynamicSmemBytes = SMEM_TOTAL;
        cfg.stream = 0;
        cfg.attrs = pdl;
        cfg.numAttrs = 1;
        cudaLaunchKernelEx(&cfg, mlp_kernel, b1, b2, b3, out, natoms);
    }
}